// round 6
// baseline (speedup 1.0000x reference)
#include <cuda_runtime.h>
#include <cstdint>

// Problem constants
#define M_DIM 8192
#define N_DIM 4096
#define K_DIM 4096
#define ALPHA 0.01f
#define INPUT_SCALE 0.05f

// GEMM tiling
#define BM 128
#define BN 128
#define BK 64
#define STRIDE 80          // padded smem row stride (bytes), conflict-free LDS
#define THREADS 256
#define K_TILES (K_DIM / BK)   // 64

// Scratch (no cudaMalloc allowed): quantized activations + packed int8 weights
__device__ int8_t g_xq[(size_t)M_DIM * K_DIM];
__device__ int8_t g_w8[(size_t)N_DIM * K_DIM];

// ---------------------------------------------------------------------------
// Kernel 0: pack weight int32 -> int8 (values fit exactly)
// ---------------------------------------------------------------------------
__global__ void pack_w_kernel(const int* __restrict__ w32, int8_t* __restrict__ w8) {
    int i = blockIdx.x * blockDim.x + threadIdx.x;  // one int4 -> char4 per thread
    const int n4 = (N_DIM * K_DIM) / 4;
    if (i >= n4) return;
    int4 v = reinterpret_cast<const int4*>(w32)[i];
    char4 o;
    o.x = (char)v.x; o.y = (char)v.y; o.z = (char)v.z; o.w = (char)v.w;
    reinterpret_cast<char4*>(w8)[i] = o;
}

// ---------------------------------------------------------------------------
// Kernel 1: quantize x (fp32) -> int8, round-half-to-even, clamp [-128,127]
// ---------------------------------------------------------------------------
__global__ void quant_kernel(const float* __restrict__ x, int8_t* __restrict__ xq) {
    int i = blockIdx.x * blockDim.x + threadIdx.x;  // one float4 per thread
    const int n4 = (M_DIM * K_DIM) / 4;
    if (i >= n4) return;
    float4 v = reinterpret_cast<const float4*>(x)[i];
    int q0 = __float2int_rn(__fdiv_rn(v.x, INPUT_SCALE));
    int q1 = __float2int_rn(__fdiv_rn(v.y, INPUT_SCALE));
    int q2 = __float2int_rn(__fdiv_rn(v.z, INPUT_SCALE));
    int q3 = __float2int_rn(__fdiv_rn(v.w, INPUT_SCALE));
    q0 = max(-128, min(127, q0));
    q1 = max(-128, min(127, q1));
    q2 = max(-128, min(127, q2));
    q3 = max(-128, min(127, q3));
    char4 o;
    o.x = (char)q0; o.y = (char)q1; o.z = (char)q2; o.w = (char)q3;
    reinterpret_cast<char4*>(xq)[i] = o;
}

// ---------------------------------------------------------------------------
// Kernel 2: int8 GEMM, C[M,N] = A[M,K] @ W[N,K]^T via mma.m16n8k32.s8
// ---------------------------------------------------------------------------

__device__ __forceinline__ void cp16(uint32_t saddr, const void* gptr) {
    asm volatile("cp.async.cg.shared.global [%0], [%1], 16;\n"
                 :: "r"(saddr), "l"(gptr));
}

__device__ __forceinline__ void mma_s8(int* c, const unsigned* a, const unsigned* b) {
    asm volatile(
        "mma.sync.aligned.m16n8k32.row.col.s32.s8.s8.s32 "
        "{%0,%1,%2,%3}, {%4,%5,%6,%7}, {%8,%9}, {%0,%1,%2,%3};\n"
        : "+r"(c[0]), "+r"(c[1]), "+r"(c[2]), "+r"(c[3])
        : "r"(a[0]), "r"(a[1]), "r"(a[2]), "r"(a[3]),
          "r"(b[0]), "r"(b[1]));
}

__global__ __launch_bounds__(THREADS, 2)
void gemm_s8_kernel(const int8_t* __restrict__ Aq,
                    const int8_t* __restrict__ W,
                    const float* __restrict__ bias,
                    float* __restrict__ out) {
    __shared__ int8_t As[2][BM * STRIDE];
    __shared__ int8_t Bs[2][BN * STRIDE];

    const int tid  = threadIdx.x;
    const int bm   = blockIdx.y * BM;
    const int bn   = blockIdx.x * BN;
    const int w    = tid >> 5;
    const int lane = tid & 31;
    const int wm   = (w >> 2) * 64;   // warp M offset (2 warps along M)
    const int wn   = (w & 3) * 32;    // warp N offset (4 warps along N)
    const int g    = lane >> 2;       // groupID  (0..7)
    const int tg   = lane & 3;        // thread-in-group (0..3)

    // Accumulators: 4 m-tiles x 4 n-tiles x 4 regs
    int acc[4][4][4];
#pragma unroll
    for (int i = 0; i < 4; i++)
#pragma unroll
        for (int j = 0; j < 4; j++)
#pragma unroll
            for (int r = 0; r < 4; r++) acc[i][j][r] = 0;

    // cp.async chunk mapping: 512 16B chunks per tile, 2 per thread
    const int c0  = tid;
    const int c1  = tid + THREADS;
    const int ra0 = c0 >> 2, ka0 = (c0 & 3) * 16;
    const int ra1 = c1 >> 2, ka1 = (c1 & 3) * 16;

    uint32_t sA[2], sB[2];
    sA[0] = (uint32_t)__cvta_generic_to_shared(&As[0][0]);
    sA[1] = (uint32_t)__cvta_generic_to_shared(&As[1][0]);
    sB[0] = (uint32_t)__cvta_generic_to_shared(&Bs[0][0]);
    sB[1] = (uint32_t)__cvta_generic_to_shared(&Bs[1][0]);

    auto load_tiles = [&](int buf, int kt) {
        const size_t kc = (size_t)kt * BK;
        cp16(sA[buf] + ra0 * STRIDE + ka0, Aq + (size_t)(bm + ra0) * K_DIM + kc + ka0);
        cp16(sA[buf] + ra1 * STRIDE + ka1, Aq + (size_t)(bm + ra1) * K_DIM + kc + ka1);
        cp16(sB[buf] + ra0 * STRIDE + ka0, W  + (size_t)(bn + ra0) * K_DIM + kc + ka0);
        cp16(sB[buf] + ra1 * STRIDE + ka1, W  + (size_t)(bn + ra1) * K_DIM + kc + ka1);
    };

    // Prefetch tile 0
    load_tiles(0, 0);
    asm volatile("cp.async.commit_group;\n");
    asm volatile("cp.async.wait_group 0;\n");
    __syncthreads();

    for (int kt = 0; kt < K_TILES; kt++) {
        const int cur = kt & 1;
        if (kt + 1 < K_TILES) {
            load_tiles(cur ^ 1, kt + 1);
            asm volatile("cp.async.commit_group;\n");
        }

        // Compute on current buffer: two k-steps of 32
#pragma unroll
        for (int ks = 0; ks < 2; ks++) {
            unsigned a[4][4];
            unsigned b[4][2];
#pragma unroll
            for (int mt = 0; mt < 4; mt++) {
                const int8_t* base = &As[cur][(wm + mt * 16 + g) * STRIDE + ks * 32 + tg * 4];
                a[mt][0] = *reinterpret_cast<const unsigned*>(base);
                a[mt][1] = *reinterpret_cast<const unsigned*>(base + 8 * STRIDE);
                a[mt][2] = *reinterpret_cast<const unsigned*>(base + 16);
                a[mt][3] = *reinterpret_cast<const unsigned*>(base + 8 * STRIDE + 16);
            }
#pragma unroll
            for (int nt = 0; nt < 4; nt++) {
                const int8_t* base = &Bs[cur][(wn + nt * 8 + g) * STRIDE + ks * 32 + tg * 4];
                b[nt][0] = *reinterpret_cast<const unsigned*>(base);
                b[nt][1] = *reinterpret_cast<const unsigned*>(base + 16);
            }
#pragma unroll
            for (int mt = 0; mt < 4; mt++)
#pragma unroll
                for (int nt = 0; nt < 4; nt++)
                    mma_s8(acc[mt][nt], a[mt], b[nt]);
        }

        asm volatile("cp.async.wait_group 0;\n");
        __syncthreads();
    }

    // Epilogue: y = ALPHA * acc + bias[n]   (fp32, vectorized float2 stores)
#pragma unroll
    for (int mt = 0; mt < 4; mt++) {
        const int m0 = bm + wm + mt * 16 + g;
#pragma unroll
        for (int nt = 0; nt < 4; nt++) {
            const int n0 = bn + wn + nt * 8 + tg * 2;
            const float b0 = bias[n0];
            const float b1 = bias[n0 + 1];
            float2 v0, v1;
            v0.x = ALPHA * (float)acc[mt][nt][0] + b0;
            v0.y = ALPHA * (float)acc[mt][nt][1] + b1;
            v1.x = ALPHA * (float)acc[mt][nt][2] + b0;
            v1.y = ALPHA * (float)acc[mt][nt][3] + b1;
            *reinterpret_cast<float2*>(&out[(size_t)m0 * N_DIM + n0])       = v0;
            *reinterpret_cast<float2*>(&out[(size_t)(m0 + 8) * N_DIM + n0]) = v1;
        }
    }
}

// ---------------------------------------------------------------------------
// Launch
// ---------------------------------------------------------------------------
extern "C" void kernel_launch(void* const* d_in, const int* in_sizes, int n_in,
                              void* d_out, int out_size) {
    const float* x    = (const float*)d_in[0];
    const int*   w32  = (const int*)d_in[1];   // weight delivered as int32
    const float* bias = (const float*)d_in[2];
    float*       out  = (float*)d_out;

    int8_t *xq, *w8;
    cudaGetSymbolAddress((void**)&xq, g_xq);
    cudaGetSymbolAddress((void**)&w8, g_w8);

    // 0) pack weights int32 -> int8
    {
        const int n4 = (N_DIM * K_DIM) / 4;
        pack_w_kernel<<<(n4 + 255) / 256, 256>>>(w32, w8);
    }
    // 1) quantize activations fp32 -> int8
    {
        const int n4 = (M_DIM * K_DIM) / 4;
        quant_kernel<<<(n4 + 255) / 256, 256>>>(x, xq);
    }
    // 2) int8 GEMM + dequant epilogue
    {
        dim3 grid(N_DIM / BN, M_DIM / BM);  // (32, 64)
        gemm_s8_kernel<<<grid, THREADS>>>(xq, w8, bias, out);
    }
}

// round 12
// speedup vs baseline: 1.0218x; 1.0218x over previous
#include <cuda_runtime.h>
#include <cstdint>

// Problem constants
#define M_DIM 8192
#define N_DIM 4096
#define K_DIM 4096
#define ALPHA 0.01f
#define INPUT_SCALE 0.05f

// ---------------------------------------------------------------------------
// Scratch (no cudaMalloc allowed)
// ---------------------------------------------------------------------------
__device__ int8_t g_xq[(size_t)M_DIM * K_DIM];
__device__ int8_t g_w8[(size_t)N_DIM * K_DIM];

// ---------------------------------------------------------------------------
// Kernel 0: pack weight int32 -> int8
// ---------------------------------------------------------------------------
__global__ void pack_w_kernel(const int* __restrict__ w32, int8_t* __restrict__ w8) {
    int i = blockIdx.x * blockDim.x + threadIdx.x;
    const int n4 = (N_DIM * K_DIM) / 4;
    if (i >= n4) return;
    int4 v = reinterpret_cast<const int4*>(w32)[i];
    char4 o;
    o.x = (char)v.x; o.y = (char)v.y; o.z = (char)v.z; o.w = (char)v.w;
    reinterpret_cast<char4*>(w8)[i] = o;
}

// ---------------------------------------------------------------------------
// Kernel 1: quantize x fp32 -> int8 (round-half-even, clamp)
// ---------------------------------------------------------------------------
__global__ void quant_kernel(const float* __restrict__ x, int8_t* __restrict__ xq) {
    int i = blockIdx.x * blockDim.x + threadIdx.x;
    const int n4 = (M_DIM * K_DIM) / 4;
    if (i >= n4) return;
    float4 v = reinterpret_cast<const float4*>(x)[i];
    int q0 = __float2int_rn(__fdiv_rn(v.x, INPUT_SCALE));
    int q1 = __float2int_rn(__fdiv_rn(v.y, INPUT_SCALE));
    int q2 = __float2int_rn(__fdiv_rn(v.z, INPUT_SCALE));
    int q3 = __float2int_rn(__fdiv_rn(v.w, INPUT_SCALE));
    q0 = max(-128, min(127, q0));
    q1 = max(-128, min(127, q1));
    q2 = max(-128, min(127, q2));
    q3 = max(-128, min(127, q3));
    char4 o;
    o.x = (char)q0; o.y = (char)q1; o.z = (char)q2; o.w = (char)q3;
    reinterpret_cast<char4*>(xq)[i] = o;
}

// ---------------------------------------------------------------------------
// Kernel 2: int8 GEMM via IMMA m16n8k32, ldmatrix fragments, 3-stage cp.async
// ---------------------------------------------------------------------------
#define BM 128
#define BN 128
#define BKB 128                       // K elems (bytes) per stage
#define STAGES 3
#define KT (K_DIM / BKB)              // 32
#define THREADS 256

#define TILE_BYTES (BM * BKB)         // 16 KB
#define SMEM_STAGE_BYTES (2 * TILE_BYTES)
#define SMEM_TOTAL (STAGES * SMEM_STAGE_BYTES)   // 96 KB

__device__ __forceinline__ uint32_t smem_u32(const void* p) {
    uint32_t a;
    asm("{ .reg .u64 t; cvta.to.shared.u64 t, %1; cvt.u32.u64 %0, t; }" : "=r"(a) : "l"(p));
    return a;
}
__device__ __forceinline__ void cp16(uint32_t saddr, const void* gptr) {
    asm volatile("cp.async.cg.shared.global [%0], [%1], 16;\n" :: "r"(saddr), "l"(gptr));
}
__device__ __forceinline__ void ldsm4(unsigned* r, uint32_t saddr) {
    asm volatile("ldmatrix.sync.aligned.m8n8.x4.shared.b16 {%0,%1,%2,%3}, [%4];"
                 : "=r"(r[0]), "=r"(r[1]), "=r"(r[2]), "=r"(r[3]) : "r"(saddr));
}
__device__ __forceinline__ void mma_s8(int* c, const unsigned* a, const unsigned* b) {
    asm volatile(
        "mma.sync.aligned.m16n8k32.row.col.s32.s8.s8.s32 "
        "{%0,%1,%2,%3}, {%4,%5,%6,%7}, {%8,%9}, {%0,%1,%2,%3};\n"
        : "+r"(c[0]), "+r"(c[1]), "+r"(c[2]), "+r"(c[3])
        : "r"(a[0]), "r"(a[1]), "r"(a[2]), "r"(a[3]),
          "r"(b[0]), "r"(b[1]));
}

__global__ __launch_bounds__(THREADS, 2)
void gemm_s8_kernel(const int8_t* __restrict__ Aq,
                    const int8_t* __restrict__ W,
                    const float* __restrict__ bias,
                    float* __restrict__ out) {
    extern __shared__ __align__(1024) int8_t smem[];
    const uint32_t sbase = smem_u32(smem);

    const int tid  = threadIdx.x;
    const int bm   = blockIdx.y * BM;
    const int bn   = blockIdx.x * BN;
    const int w    = tid >> 5;
    const int lane = tid & 31;
    const int wm   = (w >> 2) * 64;   // warp M offset (2 warps along M)
    const int wn   = (w & 3) * 32;    // warp N offset (4 warps along N)
    const int g    = lane >> 2;       // groupID  (0..7)
    const int tg   = lane & 3;        // thread-in-group

    int acc[4][4][4];
#pragma unroll
    for (int i = 0; i < 4; i++)
#pragma unroll
        for (int j = 0; j < 4; j++)
#pragma unroll
            for (int r = 0; r < 4; r++) acc[i][j][r] = 0;

    // cp.async mapping: 1024 16B chunks per tile, 4 per thread (A and B each)
    // smem layout per row: 128 bytes, swizzled col' = col ^ ((row&7)*16)
    auto stA = [&](int s) { return sbase + s * SMEM_STAGE_BYTES; };
    auto stB = [&](int s) { return sbase + s * SMEM_STAGE_BYTES + TILE_BYTES; };

    auto load_stage = [&](int s, int kt) {
        const int8_t* ga = Aq + (size_t)bm * K_DIM + (size_t)kt * BKB;
        const int8_t* gb = W  + (size_t)bn * K_DIM + (size_t)kt * BKB;
        const uint32_t sa = stA(s), sb = stB(s);
#pragma unroll
        for (int j = 0; j < 4; j++) {
            int c   = j * THREADS + tid;
            int row = c >> 3;
            int col = (c & 7) * 16;
            uint32_t soff = (uint32_t)(row * BKB + (col ^ ((row & 7) * 16)));
            cp16(sa + soff, ga + (size_t)row * K_DIM + col);
            cp16(sb + soff, gb + (size_t)row * K_DIM + col);
        }
        asm volatile("cp.async.commit_group;\n");
    };

    // ldmatrix per-lane addressing
    // lanes 0-7: rows r0..r0+7, bytes +0 | 8-15: rows +8 | 16-23: rows, bytes +16 | 24-31: rows+8, +16
    const int l15  = lane & 15;
    const int chi  = (lane & 16) ? 16 : 0;

    // Prologue: fill 2 stages
    load_stage(0, 0);
    load_stage(1, 1);

    for (int kt = 0; kt < KT; kt++) {
        const int cur = kt % STAGES;
        asm volatile("cp.async.wait_group 1;\n");
        __syncthreads();

        const uint32_t sa = stA(cur), sb = stB(cur);
#pragma unroll
        for (int ks = 0; ks < 4; ks++) {
            const int colk = ks * 32 + chi;
            unsigned a[4][4];
            unsigned bfr[4][2];
#pragma unroll
            for (int mt = 0; mt < 4; mt++) {
                int row = wm + mt * 16 + l15;
                ldsm4(a[mt], sa + row * BKB + (colk ^ ((row & 7) * 16)));
            }
#pragma unroll
            for (int j = 0; j < 2; j++) {
                unsigned t[4];
                int row = wn + j * 16 + l15;
                ldsm4(t, sb + row * BKB + (colk ^ ((row & 7) * 16)));
                bfr[2 * j][0] = t[0]; bfr[2 * j][1] = t[2];
                bfr[2 * j + 1][0] = t[1]; bfr[2 * j + 1][1] = t[3];
            }
#pragma unroll
            for (int mt = 0; mt < 4; mt++)
#pragma unroll
                for (int nt = 0; nt < 4; nt++)
                    mma_s8(acc[mt][nt], a[mt], bfr[nt]);
        }

        __syncthreads();
        if (kt + 2 < KT) load_stage((kt + 2) % STAGES, kt + 2);
    }

    // Epilogue: y = ALPHA * acc + bias[n]
#pragma unroll
    for (int mt = 0; mt < 4; mt++) {
        const int m0 = bm + wm + mt * 16 + g;
#pragma unroll
        for (int nt = 0; nt < 4; nt++) {
            const int n0 = bn + wn + nt * 8 + tg * 2;
            const float b0 = bias[n0];
            const float b1 = bias[n0 + 1];
            float2 v0, v1;
            v0.x = ALPHA * (float)acc[mt][nt][0] + b0;
            v0.y = ALPHA * (float)acc[mt][nt][1] + b1;
            v1.x = ALPHA * (float)acc[mt][nt][2] + b0;
            v1.y = ALPHA * (float)acc[mt][nt][3] + b1;
            *reinterpret_cast<float2*>(&out[(size_t)m0 * N_DIM + n0])       = v0;
            *reinterpret_cast<float2*>(&out[(size_t)(m0 + 8) * N_DIM + n0]) = v1;
        }
    }
}

// ---------------------------------------------------------------------------
// Launch
// ---------------------------------------------------------------------------
extern "C" void kernel_launch(void* const* d_in, const int* in_sizes, int n_in,
                              void* d_out, int out_size) {
    const float* x    = (const float*)d_in[0];
    const int*   w32  = (const int*)d_in[1];   // weight delivered as int32
    const float* bias = (const float*)d_in[2];
    float*       out  = (float*)d_out;

    int8_t *xq, *w8;
    cudaGetSymbolAddress((void**)&xq, g_xq);
    cudaGetSymbolAddress((void**)&w8, g_w8);

    cudaFuncSetAttribute(gemm_s8_kernel, cudaFuncAttributeMaxDynamicSharedMemorySize,
                         SMEM_TOTAL);

    {   // 0) pack weights int32 -> int8
        const int n4 = (N_DIM * K_DIM) / 4;
        pack_w_kernel<<<(n4 + 255) / 256, 256>>>(w32, w8);
    }
    {   // 1) quantize activations fp32 -> int8
        const int n4 = (M_DIM * K_DIM) / 4;
        quant_kernel<<<(n4 + 255) / 256, 256>>>(x, xq);
    }
    {   // 2) int8 GEMM + dequant epilogue
        dim3 grid(N_DIM / BN, M_DIM / BM);  // (32, 64)
        gemm_s8_kernel<<<grid, THREADS, SMEM_TOTAL>>>(xq, w8, bias, out);
    }
}

// round 13
// speedup vs baseline: 2.5286x; 2.4746x over previous
#include <cuda_runtime.h>
#include <cuda_fp16.h>
#include <cstdint>

// Problem constants
#define M_DIM 8192
#define N_DIM 4096
#define K_DIM 4096
#define ALPHA 0.01f
#define INPUT_SCALE 0.05f

// ---------------------------------------------------------------------------
// Scratch (no cudaMalloc allowed): fp16 copies of quantized A and W
// ---------------------------------------------------------------------------
__device__ __half g_xh[(size_t)M_DIM * K_DIM];   // 67 MB
__device__ __half g_wh[(size_t)N_DIM * K_DIM];   // 33.5 MB

// ---------------------------------------------------------------------------
// Kernel 0: weight int32 -> fp16 (values in [-127,127], exact in fp16)
// ---------------------------------------------------------------------------
__global__ void pack_w_kernel(const int* __restrict__ w32, __half* __restrict__ wh) {
    int i = blockIdx.x * blockDim.x + threadIdx.x;
    const int n4 = (N_DIM * K_DIM) / 4;
    if (i >= n4) return;
    int4 v = reinterpret_cast<const int4*>(w32)[i];
    __half2 h0 = __halves2half2(__int2half_rn(v.x), __int2half_rn(v.y));
    __half2 h1 = __halves2half2(__int2half_rn(v.z), __int2half_rn(v.w));
    uint2 o;
    o.x = *reinterpret_cast<unsigned*>(&h0);
    o.y = *reinterpret_cast<unsigned*>(&h1);
    reinterpret_cast<uint2*>(wh)[i] = o;
}

// ---------------------------------------------------------------------------
// Kernel 1: quantize x fp32 -> int (round-half-even, clamp) -> fp16 (exact)
// ---------------------------------------------------------------------------
__global__ void quant_kernel(const float* __restrict__ x, __half* __restrict__ xh) {
    int i = blockIdx.x * blockDim.x + threadIdx.x;
    const int n4 = (M_DIM * K_DIM) / 4;
    if (i >= n4) return;
    float4 v = reinterpret_cast<const float4*>(x)[i];
    int q0 = __float2int_rn(__fdiv_rn(v.x, INPUT_SCALE));
    int q1 = __float2int_rn(__fdiv_rn(v.y, INPUT_SCALE));
    int q2 = __float2int_rn(__fdiv_rn(v.z, INPUT_SCALE));
    int q3 = __float2int_rn(__fdiv_rn(v.w, INPUT_SCALE));
    q0 = max(-128, min(127, q0));
    q1 = max(-128, min(127, q1));
    q2 = max(-128, min(127, q2));
    q3 = max(-128, min(127, q3));
    __half2 h0 = __halves2half2(__int2half_rn(q0), __int2half_rn(q1));
    __half2 h1 = __halves2half2(__int2half_rn(q2), __int2half_rn(q3));
    uint2 o;
    o.x = *reinterpret_cast<unsigned*>(&h0);
    o.y = *reinterpret_cast<unsigned*>(&h1);
    reinterpret_cast<uint2*>(xh)[i] = o;
}

// ---------------------------------------------------------------------------
// Kernel 2: fp16 GEMM via HMMA m16n8k16 (f32 accum), ldmatrix, 3-stage cp.async
//   C[M,N] = A[M,K] @ W[N,K]^T  (A,W hold exact small integers)
// ---------------------------------------------------------------------------
#define BM 128
#define BN 128
#define BKE 64                        // K elems per stage (fp16 => 128 bytes/row)
#define ROWB 128                      // bytes per smem row
#define STAGES 3
#define KT (K_DIM / BKE)              // 64
#define THREADS 256

#define TILE_BYTES (BM * ROWB)        // 16 KB
#define SMEM_STAGE_BYTES (2 * TILE_BYTES)
#define SMEM_TOTAL (STAGES * SMEM_STAGE_BYTES)   // 96 KB

__device__ __forceinline__ uint32_t smem_u32(const void* p) {
    uint32_t a;
    asm("{ .reg .u64 t; cvta.to.shared.u64 t, %1; cvt.u32.u64 %0, t; }" : "=r"(a) : "l"(p));
    return a;
}
__device__ __forceinline__ void cp16(uint32_t saddr, const void* gptr) {
    asm volatile("cp.async.cg.shared.global [%0], [%1], 16;\n" :: "r"(saddr), "l"(gptr));
}
__device__ __forceinline__ void ldsm4(unsigned* r, uint32_t saddr) {
    asm volatile("ldmatrix.sync.aligned.m8n8.x4.shared.b16 {%0,%1,%2,%3}, [%4];"
                 : "=r"(r[0]), "=r"(r[1]), "=r"(r[2]), "=r"(r[3]) : "r"(saddr));
}
__device__ __forceinline__ void mma_f16(float* c, const unsigned* a, const unsigned* b) {
    asm volatile(
        "mma.sync.aligned.m16n8k16.row.col.f32.f16.f16.f32 "
        "{%0,%1,%2,%3}, {%4,%5,%6,%7}, {%8,%9}, {%0,%1,%2,%3};\n"
        : "+f"(c[0]), "+f"(c[1]), "+f"(c[2]), "+f"(c[3])
        : "r"(a[0]), "r"(a[1]), "r"(a[2]), "r"(a[3]),
          "r"(b[0]), "r"(b[1]));
}

__global__ __launch_bounds__(THREADS, 2)
void gemm_f16_kernel(const __half* __restrict__ Ah,
                     const __half* __restrict__ Wh,
                     const float* __restrict__ bias,
                     float* __restrict__ out) {
    extern __shared__ __align__(1024) int8_t smem[];
    const uint32_t sbase = smem_u32(smem);

    const int tid  = threadIdx.x;
    const int bm   = blockIdx.y * BM;
    const int bn   = blockIdx.x * BN;
    const int w    = tid >> 5;
    const int lane = tid & 31;
    const int wm   = (w >> 2) * 64;   // warp M offset (2 warps along M)
    const int wn   = (w & 3) * 32;    // warp N offset (4 warps along N)
    const int g    = lane >> 2;       // groupID  (0..7)
    const int tg   = lane & 3;        // thread-in-group

    float acc[4][4][4];
#pragma unroll
    for (int i = 0; i < 4; i++)
#pragma unroll
        for (int j = 0; j < 4; j++)
#pragma unroll
            for (int r = 0; r < 4; r++) acc[i][j][r] = 0.0f;

    // byte-view of global tiles (rows of 128 bytes = 64 fp16)
    const int8_t* gA = reinterpret_cast<const int8_t*>(Ah);
    const int8_t* gB = reinterpret_cast<const int8_t*>(Wh);
    const size_t rowbytes = (size_t)K_DIM * 2;

    auto stA = [&](int s) { return sbase + s * SMEM_STAGE_BYTES; };
    auto stB = [&](int s) { return sbase + s * SMEM_STAGE_BYTES + TILE_BYTES; };

    auto load_stage = [&](int s, int kt) {
        const int8_t* ga = gA + (size_t)bm * rowbytes + (size_t)kt * ROWB;
        const int8_t* gb = gB + (size_t)bn * rowbytes + (size_t)kt * ROWB;
        const uint32_t sa = stA(s), sb = stB(s);
#pragma unroll
        for (int j = 0; j < 4; j++) {
            int c   = j * THREADS + tid;
            int row = c >> 3;
            int col = (c & 7) * 16;
            uint32_t soff = (uint32_t)(row * ROWB + (col ^ ((row & 7) * 16)));
            cp16(sa + soff, ga + (size_t)row * rowbytes + col);
            cp16(sb + soff, gb + (size_t)row * rowbytes + col);
        }
        asm volatile("cp.async.commit_group;\n");
    };

    // ldmatrix lane addressing: lanes 0-15 -> 16 rows @ +0B, lanes 16-31 -> +16B
    const int l15 = lane & 15;
    const int chi = (lane & 16) ? 16 : 0;

    load_stage(0, 0);
    load_stage(1, 1);

    for (int kt = 0; kt < KT; kt++) {
        const int cur = kt % STAGES;
        asm volatile("cp.async.wait_group 1;\n");
        __syncthreads();

        const uint32_t sa = stA(cur), sb = stB(cur);
#pragma unroll
        for (int ks = 0; ks < 4; ks++) {           // 4 x (K=16 fp16 = 32B)
            const int colk = ks * 32 + chi;
            unsigned a[4][4];
            unsigned bfr[4][2];
#pragma unroll
            for (int mt = 0; mt < 4; mt++) {
                int row = wm + mt * 16 + l15;
                ldsm4(a[mt], sa + row * ROWB + (colk ^ ((row & 7) * 16)));
            }
#pragma unroll
            for (int j = 0; j < 2; j++) {
                unsigned t[4];
                int row = wn + j * 16 + l15;
                ldsm4(t, sb + row * ROWB + (colk ^ ((row & 7) * 16)));
                bfr[2 * j][0]     = t[0]; bfr[2 * j][1]     = t[2];
                bfr[2 * j + 1][0] = t[1]; bfr[2 * j + 1][1] = t[3];
            }
#pragma unroll
            for (int mt = 0; mt < 4; mt++)
#pragma unroll
                for (int nt = 0; nt < 4; nt++)
                    mma_f16(acc[mt][nt], a[mt], bfr[nt]);
        }

        __syncthreads();
        if (kt + 2 < KT) load_stage((kt + 2) % STAGES, kt + 2);
    }

    // Epilogue: y = ALPHA * acc + bias[n]
#pragma unroll
    for (int mt = 0; mt < 4; mt++) {
        const int m0 = bm + wm + mt * 16 + g;
#pragma unroll
        for (int nt = 0; nt < 4; nt++) {
            const int n0 = bn + wn + nt * 8 + tg * 2;
            const float b0 = bias[n0];
            const float b1 = bias[n0 + 1];
            float2 v0, v1;
            v0.x = ALPHA * acc[mt][nt][0] + b0;
            v0.y = ALPHA * acc[mt][nt][1] + b1;
            v1.x = ALPHA * acc[mt][nt][2] + b0;
            v1.y = ALPHA * acc[mt][nt][3] + b1;
            *reinterpret_cast<float2*>(&out[(size_t)m0 * N_DIM + n0])       = v0;
            *reinterpret_cast<float2*>(&out[(size_t)(m0 + 8) * N_DIM + n0]) = v1;
        }
    }
}

// ---------------------------------------------------------------------------
// Launch
// ---------------------------------------------------------------------------
extern "C" void kernel_launch(void* const* d_in, const int* in_sizes, int n_in,
                              void* d_out, int out_size) {
    const float* x    = (const float*)d_in[0];
    const int*   w32  = (const int*)d_in[1];   // weight delivered as int32
    const float* bias = (const float*)d_in[2];
    float*       out  = (float*)d_out;

    __half *xh, *wh;
    cudaGetSymbolAddress((void**)&xh, g_xh);
    cudaGetSymbolAddress((void**)&wh, g_wh);

    cudaFuncSetAttribute(gemm_f16_kernel, cudaFuncAttributeMaxDynamicSharedMemorySize,
                         SMEM_TOTAL);

    {   // 0) weights int32 -> fp16
        const int n4 = (N_DIM * K_DIM) / 4;
        pack_w_kernel<<<(n4 + 255) / 256, 256>>>(w32, wh);
    }
    {   // 1) quantize activations fp32 -> fp16 (integer-valued)
        const int n4 = (M_DIM * K_DIM) / 4;
        quant_kernel<<<(n4 + 255) / 256, 256>>>(x, xh);
    }
    {   // 2) fp16 HMMA GEMM + dequant epilogue
        dim3 grid(N_DIM / BN, M_DIM / BM);  // (32, 64)
        gemm_f16_kernel<<<grid, THREADS, SMEM_TOTAL>>>(xh, wh, bias, out);
    }
}